// round 6
// baseline (speedup 1.0000x reference)
#include <cuda_runtime.h>
#include <cstddef>

// Problem constants (fixed by setup_inputs)
#define B_   32
#define CIN  256
#define COUT 512
#define H_   64
#define W_   64
#define HW   (H_*W_)          // 4096
#define GROUPS 9
#define IN_CPG 28             // 252 channels used, 28 per group
#define OUT_CPG 56            // 504 channels, 56 per group; 504..511 -> group 4

#define GSUM_BLOCKS 1152      // B_*GROUPS*(HW/4) / 256
#define WEFF_BLOCKS 576       // 4608 warps / 8
#define PREP_BLOCKS (GSUM_BLOCKS + WEFF_BLOCKS)

#define WSTRIDE 20            // floats per o-row in w_dup2 (9 dup pairs + pad, 80B)
#define OSPLIT  4             // o-dimension split across blockIdx.z
#define OPB     (COUT / OSPLIT)   // 128 o's per block

// Scratch: s (B,9,H,W) = 4.5 MiB, W_eff (512,9)
__device__ float g_s[B_ * GROUPS * HW];
__device__ float g_we[COUT * GROUPS];

// ---------------------------------------------------------------------------
// Fused prep kernel.
// Blocks [0, GSUM_BLOCKS):  s[b,g,h,w] = sum_{k<28} x[b, 28g+k, h, w]
// Blocks [GSUM_BLOCKS, ..): W_eff[o,g] = sum w_pw[o, 56g..56g+55] (+504..511 for g=4)
// x is read-once (128 MiB): use streaming loads to keep L2 for s.
// ---------------------------------------------------------------------------
__global__ __launch_bounds__(256) void shiftconv_prep(const float4* __restrict__ x4,
                                                      const float*  __restrict__ w) {
    const int bx = blockIdx.x;
    if (bx < GSUM_BLOCKS) {
        int idx = bx * 256 + threadIdx.x;                // over B*9*(HW/4)
        int hw4 = idx & (HW / 4 - 1);                    // 0..1023
        int t   = idx >> 10;                             // b*9+g
        int b = t / GROUPS, g = t % GROUPS;
        const float4* p = x4 + ((size_t)(b * CIN + g * IN_CPG) << 10) + hw4;
        float4 a = make_float4(0.f, 0.f, 0.f, 0.f);
#pragma unroll
        for (int k = 0; k < IN_CPG; k++) {
            float4 v = __ldcs(p + ((size_t)k << 10));    // streaming: read-once
            a.x += v.x; a.y += v.y; a.z += v.z; a.w += v.w;
        }
        reinterpret_cast<float4*>(g_s)[(size_t)t * (HW / 4) + hw4] = a;
    } else {
        // warp per (o,g)
        const int warp = (bx - GSUM_BLOCKS) * 8 + (threadIdx.x >> 5);
        const int lane = threadIdx.x & 31;
        const int o = warp / GROUPS;
        const int g = warp % GROUPS;
        const float* row = w + (size_t)o * COUT;
        float s = 0.f;
        if (lane < IN_CPG)
            s = row[g * OUT_CPG + lane] + row[g * OUT_CPG + 28 + lane];
        if (g == 4 && lane < 8)
            s += row[504 + lane];
#pragma unroll
        for (int off = 16; off > 0; off >>= 1)
            s += __shfl_xor_sync(0xffffffffu, s, off);
        if (lane == 0) g_we[warp] = s;
    }
}

// ---------------------------------------------------------------------------
// Kernel C: y[b,o,h,w] = sum_g W_eff[o,g] * s[b,g, h+dy, w+dx]
// Block = (b, h, oz): one output row, 128 of 512 o's. 256 threads:
// w0=(tid&15)*4 (4 consecutive w), och=tid>>4, o = oz*128 + oo*16 + och.
// f32x2 packed over PIXELS; weights duplicated+contiguous per o in shared
// (4x LDS.128 + 1x LDS.64 per o). Shared cut 43KB -> ~13KB so residency is
// register-limited (4 blocks/SM, 32 warps) instead of smem-limited (2):
// prior profile showed no pipe >60% => latency-bound on store chains.
// y written once with st.global.cs (don't thrash L2; y >> L2).
// ---------------------------------------------------------------------------
__global__ __launch_bounds__(256) void shiftconv_pw(float* __restrict__ y) {
    __shared__ float w_dup2[OPB * WSTRIDE];              // 10,240 B
    __shared__ float s_sh[GROUPS][W_ + 2];               // 2,376 B (halo cols)

    const int b  = blockIdx.x;                           // 0..31
    const int h  = blockIdx.y;                           // 0..63
    const int ob = blockIdx.z * OPB;                     // o base: 0,128,256,384
    const int tid = threadIdx.x;

    // zero s_sh halo
    for (int i = tid; i < GROUPS * (W_ + 2); i += 256)
        (&s_sh[0][0])[i] = 0.f;
    // weights: g_we is [o][g]; duplicated pair per (o,g), contiguous in o-row
    for (int i = tid; i < OPB * GROUPS; i += 256) {
        int ol = i / GROUPS, g = i - ol * GROUPS;
        float v = g_we[(ob + ol) * GROUPS + g];
        w_dup2[ol * WSTRIDE + 2 * g]     = v;
        w_dup2[ol * WSTRIDE + 2 * g + 1] = v;
    }
    __syncthreads();

    // stage the single s row each group needs: row h + g/3 - 1
    for (int i = tid; i < GROUPS * W_; i += 256) {
        int g = i >> 6, wc = i & 63;
        int hp = h + g / 3 - 1;
        if ((unsigned)hp < (unsigned)H_)
            s_sh[g][wc + 1] = g_s[((size_t)(b * GROUPS + g) << 12) + (hp << 6) + wc];
    }
    __syncthreads();

    const int w0  = (tid & 15) * 4;
    const int och = tid >> 4;                            // 0..15

    // pack shifted s pixel pairs: idx w0+dx+1 = w0 + g%3
    unsigned long long sv2[GROUPS][2];
#pragma unroll
    for (int g = 0; g < GROUPS; g++) {
        const float* r = &s_sh[g][w0 + (g % 3)];
        asm("mov.b64 %0, {%1, %2};" : "=l"(sv2[g][0]) : "f"(r[0]), "f"(r[1]));
        asm("mov.b64 %0, {%1, %2};" : "=l"(sv2[g][1]) : "f"(r[2]), "f"(r[3]));
    }

    float4* yp = reinterpret_cast<float4*>(
        y + ((size_t)b * COUT + ob + och) * HW + h * W_ + w0);
#pragma unroll
    for (int oo = 0; oo < OPB / 16; oo++) {              // 8 iterations
        const int ol = oo * 16 + och;
        const float* wrow = &w_dup2[ol * WSTRIDE];
        // 9 duplicated weight pairs via 4x LDS.128 + 1x LDS.64
        ulonglong2 wA = *reinterpret_cast<const ulonglong2*>(wrow);      // g0,g1
        ulonglong2 wB = *reinterpret_cast<const ulonglong2*>(wrow + 4);  // g2,g3
        ulonglong2 wC = *reinterpret_cast<const ulonglong2*>(wrow + 8);  // g4,g5
        ulonglong2 wD = *reinterpret_cast<const ulonglong2*>(wrow + 12); // g6,g7
        unsigned long long wE =
            *reinterpret_cast<const unsigned long long*>(wrow + 16);     // g8

        unsigned long long a0 = 0ull, a1 = 0ull;
        asm("fma.rn.f32x2 %0, %1, %2, %0;" : "+l"(a0) : "l"(wA.x), "l"(sv2[0][0]));
        asm("fma.rn.f32x2 %0, %1, %2, %0;" : "+l"(a1) : "l"(wA.x), "l"(sv2[0][1]));
        asm("fma.rn.f32x2 %0, %1, %2, %0;" : "+l"(a0) : "l"(wA.y), "l"(sv2[1][0]));
        asm("fma.rn.f32x2 %0, %1, %2, %0;" : "+l"(a1) : "l"(wA.y), "l"(sv2[1][1]));
        asm("fma.rn.f32x2 %0, %1, %2, %0;" : "+l"(a0) : "l"(wB.x), "l"(sv2[2][0]));
        asm("fma.rn.f32x2 %0, %1, %2, %0;" : "+l"(a1) : "l"(wB.x), "l"(sv2[2][1]));
        asm("fma.rn.f32x2 %0, %1, %2, %0;" : "+l"(a0) : "l"(wB.y), "l"(sv2[3][0]));
        asm("fma.rn.f32x2 %0, %1, %2, %0;" : "+l"(a1) : "l"(wB.y), "l"(sv2[3][1]));
        asm("fma.rn.f32x2 %0, %1, %2, %0;" : "+l"(a0) : "l"(wC.x), "l"(sv2[4][0]));
        asm("fma.rn.f32x2 %0, %1, %2, %0;" : "+l"(a1) : "l"(wC.x), "l"(sv2[4][1]));
        asm("fma.rn.f32x2 %0, %1, %2, %0;" : "+l"(a0) : "l"(wC.y), "l"(sv2[5][0]));
        asm("fma.rn.f32x2 %0, %1, %2, %0;" : "+l"(a1) : "l"(wC.y), "l"(sv2[5][1]));
        asm("fma.rn.f32x2 %0, %1, %2, %0;" : "+l"(a0) : "l"(wD.x), "l"(sv2[6][0]));
        asm("fma.rn.f32x2 %0, %1, %2, %0;" : "+l"(a1) : "l"(wD.x), "l"(sv2[6][1]));
        asm("fma.rn.f32x2 %0, %1, %2, %0;" : "+l"(a0) : "l"(wD.y), "l"(sv2[7][0]));
        asm("fma.rn.f32x2 %0, %1, %2, %0;" : "+l"(a1) : "l"(wD.y), "l"(sv2[7][1]));
        asm("fma.rn.f32x2 %0, %1, %2, %0;" : "+l"(a0) : "l"(wE),   "l"(sv2[8][0]));
        asm("fma.rn.f32x2 %0, %1, %2, %0;" : "+l"(a1) : "l"(wE),   "l"(sv2[8][1]));

        float4 out;
        asm("mov.b64 {%0, %1}, %2;" : "=f"(out.x), "=f"(out.y) : "l"(a0));
        asm("mov.b64 {%0, %1}, %2;" : "=f"(out.z), "=f"(out.w) : "l"(a1));
        __stcs(yp + (size_t)oo * 16 * (HW / 4), out);    // streaming store, o stride 16
    }
}

// ---------------------------------------------------------------------------
extern "C" void kernel_launch(void* const* d_in, const int* in_sizes, int n_in,
                              void* d_out, int out_size) {
    const float* x = (const float*)d_in[0];
    const float* w = (const float*)d_in[1];
    if (n_in >= 2 && in_sizes[0] == COUT * COUT) {       // order safety
        const float* t = x; x = w; w = t;
    }
    float* y = (float*)d_out;

    shiftconv_prep<<<PREP_BLOCKS, 256>>>((const float4*)x, w);
    shiftconv_pw<<<dim3(B_, H_, OSPLIT), 256>>>(y);
}

// round 7
// speedup vs baseline: 1.2682x; 1.2682x over previous
#include <cuda_runtime.h>
#include <cstddef>

// Problem constants (fixed by setup_inputs)
#define B_   32
#define CIN  256
#define COUT 512
#define H_   64
#define W_   64
#define HW   (H_*W_)          // 4096
#define GROUPS 9
#define IN_CPG 28             // 252 channels used, 28 per group
#define OUT_CPG 56            // 504 channels, 56 per group; 504..511 -> group 4

#define GSUM_BLOCKS 1152      // B_*GROUPS*(HW/4) / 256
#define WEFF_BLOCKS 576       // 4608 warps / 8
#define PREP_BLOCKS (GSUM_BLOCKS + WEFF_BLOCKS)

#define WSTRIDE 20            // floats per o-row in w_dup2 (9 dup pairs + pad, 80B)
#define PW_GRID 512           // persistent: all resident at 4 blocks/SM, 4 (b,h) pairs each

// Scratch: s (B,9,H,W) = 4.5 MiB, W_eff (512,9)
__device__ float g_s[B_ * GROUPS * HW];
__device__ float g_we[COUT * GROUPS];

// ---------------------------------------------------------------------------
// Fused prep kernel.
// Blocks [0, GSUM_BLOCKS):  s[b,g,h,w] = sum_{k<28} x[b, 28g+k, h, w]
// Blocks [GSUM_BLOCKS, ..): W_eff[o,g] = sum w_pw[o, 56g..56g+55] (+504..511 for g=4)
// x is read-once (128 MiB): streaming loads keep L2 for s. (Measured ~-6us.)
// ---------------------------------------------------------------------------
__global__ __launch_bounds__(256) void shiftconv_prep(const float4* __restrict__ x4,
                                                      const float*  __restrict__ w) {
    const int bx = blockIdx.x;
    if (bx < GSUM_BLOCKS) {
        int idx = bx * 256 + threadIdx.x;                // over B*9*(HW/4)
        int hw4 = idx & (HW / 4 - 1);                    // 0..1023
        int t   = idx >> 10;                             // b*9+g
        int b = t / GROUPS, g = t % GROUPS;
        const float4* p = x4 + ((size_t)(b * CIN + g * IN_CPG) << 10) + hw4;
        float4 a = make_float4(0.f, 0.f, 0.f, 0.f);
#pragma unroll
        for (int k = 0; k < IN_CPG; k++) {
            float4 v = __ldcs(p + ((size_t)k << 10));    // streaming: read-once
            a.x += v.x; a.y += v.y; a.z += v.z; a.w += v.w;
        }
        reinterpret_cast<float4*>(g_s)[(size_t)t * (HW / 4) + hw4] = a;
    } else {
        // warp per (o,g)
        const int warp = (bx - GSUM_BLOCKS) * 8 + (threadIdx.x >> 5);
        const int lane = threadIdx.x & 31;
        const int o = warp / GROUPS;
        const int g = warp % GROUPS;
        const float* row = w + (size_t)o * COUT;
        float s = 0.f;
        if (lane < IN_CPG)
            s = row[g * OUT_CPG + lane] + row[g * OUT_CPG + 28 + lane];
        if (g == 4 && lane < 8)
            s += row[504 + lane];
#pragma unroll
        for (int off = 16; off > 0; off >>= 1)
            s += __shfl_xor_sync(0xffffffffu, s, off);
        if (lane == 0) g_we[warp] = s;
    }
}

// ---------------------------------------------------------------------------
// Kernel C (persistent): y[b,o,h,w] = sum_g W_eff[o,g] * s[b,g, h+dy, w+dx]
// Grid = 512 blocks, all co-resident (4/SM). Weights staged into shared ONCE
// per block (prologue was 76 vs 48 loop instrs/thread in the per-row version;
// now amortized 4x). Each block loops over 4 (b,h) pairs, restaging only the
// 576-float s row slice per iteration. o-loop identical to the best (R5)
// codegen: f32x2 over pixels, 4x LDS.128 + 1x LDS.64 weights/o, unroll 4.
// ---------------------------------------------------------------------------
__global__ __launch_bounds__(256) void shiftconv_pw(float* __restrict__ y) {
    __shared__ float w_dup2[COUT * WSTRIDE];             // 40,960 B
    __shared__ float s_sh[GROUPS][W_ + 2];               // 2,376 B (halo cols)

    const int tid = threadIdx.x;

    // zero halo columns once (cols 0 and W_+1 are never overwritten)
    for (int i = tid; i < GROUPS * (W_ + 2); i += 256)
        (&s_sh[0][0])[i] = 0.f;
    // weights once: g_we is [o][g]; duplicated pair per (o,g), contiguous o-row
    for (int i = tid; i < COUT * GROUPS; i += 256) {
        int o = i / GROUPS, g = i - o * GROUPS;
        float v = g_we[i];
        w_dup2[o * WSTRIDE + 2 * g]     = v;
        w_dup2[o * WSTRIDE + 2 * g + 1] = v;
    }

    const int w0  = (tid & 15) * 4;
    const int och = tid >> 4;                            // 0..15

    for (int idx = blockIdx.x; idx < B_ * H_; idx += PW_GRID) {
        const int b = idx >> 6;
        const int h = idx & 63;

        __syncthreads();                                 // prior s_sh reads done (covers weights on iter 0)
        // stage the single s row each group needs: row h + g/3 - 1
        // unconditional write: out-of-range rows become 0 (no stale reuse)
        for (int i = tid; i < GROUPS * W_; i += 256) {
            int g = i >> 6, wc = i & 63;
            int hp = h + g / 3 - 1;
            s_sh[g][wc + 1] = ((unsigned)hp < (unsigned)H_)
                ? g_s[((size_t)(b * GROUPS + g) << 12) + (hp << 6) + wc] : 0.f;
        }
        __syncthreads();

        // pack shifted s pixel pairs: idx w0+dx+1 = w0 + g%3
        unsigned long long sv2[GROUPS][2];
#pragma unroll
        for (int g = 0; g < GROUPS; g++) {
            const float* r = &s_sh[g][w0 + (g % 3)];
            asm("mov.b64 %0, {%1, %2};" : "=l"(sv2[g][0]) : "f"(r[0]), "f"(r[1]));
            asm("mov.b64 %0, {%1, %2};" : "=l"(sv2[g][1]) : "f"(r[2]), "f"(r[3]));
        }

        float4* yp = reinterpret_cast<float4*>(
            y + ((size_t)b * COUT + och) * HW + h * W_ + w0);
#pragma unroll 4
        for (int oo = 0; oo < 32; oo++) {
            const int o = oo * 16 + och;
            const float* wrow = &w_dup2[o * WSTRIDE];
            // 9 duplicated weight pairs via 4x LDS.128 + 1x LDS.64
            ulonglong2 wA = *reinterpret_cast<const ulonglong2*>(wrow);      // g0,g1
            ulonglong2 wB = *reinterpret_cast<const ulonglong2*>(wrow + 4);  // g2,g3
            ulonglong2 wC = *reinterpret_cast<const ulonglong2*>(wrow + 8);  // g4,g5
            ulonglong2 wD = *reinterpret_cast<const ulonglong2*>(wrow + 12); // g6,g7
            unsigned long long wE =
                *reinterpret_cast<const unsigned long long*>(wrow + 16);     // g8

            unsigned long long a0 = 0ull, a1 = 0ull;
            asm("fma.rn.f32x2 %0, %1, %2, %0;" : "+l"(a0) : "l"(wA.x), "l"(sv2[0][0]));
            asm("fma.rn.f32x2 %0, %1, %2, %0;" : "+l"(a1) : "l"(wA.x), "l"(sv2[0][1]));
            asm("fma.rn.f32x2 %0, %1, %2, %0;" : "+l"(a0) : "l"(wA.y), "l"(sv2[1][0]));
            asm("fma.rn.f32x2 %0, %1, %2, %0;" : "+l"(a1) : "l"(wA.y), "l"(sv2[1][1]));
            asm("fma.rn.f32x2 %0, %1, %2, %0;" : "+l"(a0) : "l"(wB.x), "l"(sv2[2][0]));
            asm("fma.rn.f32x2 %0, %1, %2, %0;" : "+l"(a1) : "l"(wB.x), "l"(sv2[2][1]));
            asm("fma.rn.f32x2 %0, %1, %2, %0;" : "+l"(a0) : "l"(wB.y), "l"(sv2[3][0]));
            asm("fma.rn.f32x2 %0, %1, %2, %0;" : "+l"(a1) : "l"(wB.y), "l"(sv2[3][1]));
            asm("fma.rn.f32x2 %0, %1, %2, %0;" : "+l"(a0) : "l"(wC.x), "l"(sv2[4][0]));
            asm("fma.rn.f32x2 %0, %1, %2, %0;" : "+l"(a1) : "l"(wC.x), "l"(sv2[4][1]));
            asm("fma.rn.f32x2 %0, %1, %2, %0;" : "+l"(a0) : "l"(wC.y), "l"(sv2[5][0]));
            asm("fma.rn.f32x2 %0, %1, %2, %0;" : "+l"(a1) : "l"(wC.y), "l"(sv2[5][1]));
            asm("fma.rn.f32x2 %0, %1, %2, %0;" : "+l"(a0) : "l"(wD.x), "l"(sv2[6][0]));
            asm("fma.rn.f32x2 %0, %1, %2, %0;" : "+l"(a1) : "l"(wD.x), "l"(sv2[6][1]));
            asm("fma.rn.f32x2 %0, %1, %2, %0;" : "+l"(a0) : "l"(wD.y), "l"(sv2[7][0]));
            asm("fma.rn.f32x2 %0, %1, %2, %0;" : "+l"(a1) : "l"(wD.y), "l"(sv2[7][1]));
            asm("fma.rn.f32x2 %0, %1, %2, %0;" : "+l"(a0) : "l"(wE),   "l"(sv2[8][0]));
            asm("fma.rn.f32x2 %0, %1, %2, %0;" : "+l"(a1) : "l"(wE),   "l"(sv2[8][1]));

            float4 out;
            asm("mov.b64 {%0, %1}, %2;" : "=f"(out.x), "=f"(out.y) : "l"(a0));
            asm("mov.b64 {%0, %1}, %2;" : "=f"(out.z), "=f"(out.w) : "l"(a1));
            yp[(size_t)oo * 16 * (HW / 4)] = out;        // o stride 16
        }
    }
}

// ---------------------------------------------------------------------------
extern "C" void kernel_launch(void* const* d_in, const int* in_sizes, int n_in,
                              void* d_out, int out_size) {
    const float* x = (const float*)d_in[0];
    const float* w = (const float*)d_in[1];
    if (n_in >= 2 && in_sizes[0] == COUT * COUT) {       // order safety
        const float* t = x; x = w; w = t;
    }
    float* y = (float*)d_out;

    shiftconv_prep<<<PREP_BLOCKS, 256>>>((const float4*)x, w);
    shiftconv_pw<<<PW_GRID, 256>>>(y);
}

// round 8
// speedup vs baseline: 1.3615x; 1.0736x over previous
#include <cuda_runtime.h>
#include <cstddef>

// Problem constants (fixed by setup_inputs)
#define B_   32
#define CIN  256
#define COUT 512
#define H_   64
#define W_   64
#define HW   (H_*W_)          // 4096
#define GROUPS 9
#define IN_CPG 28             // 252 channels used, 28 per group
#define OUT_CPG 56            // 504 channels, 56 per group; 504..511 -> group 4

#define GSUM_BLOCKS 1152      // B_*GROUPS*(HW/4) / 256
#define WEFF_BLOCKS 576       // 4608 warps / 8
#define PREP_BLOCKS (GSUM_BLOCKS + WEFF_BLOCKS)

#define WSTRIDE 20            // floats per o-row in w_dup2 (9 dup pairs + pad, 80B)

// Scratch: s (B,9,H,W) = 4.5 MiB, W_eff (512,9)
__device__ float g_s[B_ * GROUPS * HW];
__device__ float g_we[COUT * GROUPS];

// ---------------------------------------------------------------------------
// Fused prep kernel (R6-proven, ~21us).
// Blocks [0, GSUM_BLOCKS):  s[b,g,h,w] = sum_{k<28} x[b, 28g+k, h, w]
// Blocks [GSUM_BLOCKS, ..): W_eff[o,g] = sum w_pw[o, 56g..56g+55] (+504..511 for g=4)
// x is read-once (128 MiB): streaming loads keep L2 for s.
// ---------------------------------------------------------------------------
__global__ __launch_bounds__(256) void shiftconv_prep(const float4* __restrict__ x4,
                                                      const float*  __restrict__ w) {
    const int bx = blockIdx.x;
    if (bx < GSUM_BLOCKS) {
        int idx = bx * 256 + threadIdx.x;                // over B*9*(HW/4)
        int hw4 = idx & (HW / 4 - 1);                    // 0..1023
        int t   = idx >> 10;                             // b*9+g
        int b = t / GROUPS, g = t % GROUPS;
        const float4* p = x4 + ((size_t)(b * CIN + g * IN_CPG) << 10) + hw4;
        float4 a = make_float4(0.f, 0.f, 0.f, 0.f);
#pragma unroll
        for (int k = 0; k < IN_CPG; k++) {
            float4 v = __ldcs(p + ((size_t)k << 10));    // streaming: read-once
            a.x += v.x; a.y += v.y; a.z += v.z; a.w += v.w;
        }
        reinterpret_cast<float4*>(g_s)[(size_t)t * (HW / 4) + hw4] = a;
    } else {
        // warp per (o,g)
        const int warp = (bx - GSUM_BLOCKS) * 8 + (threadIdx.x >> 5);
        const int lane = threadIdx.x & 31;
        const int o = warp / GROUPS;
        const int g = warp % GROUPS;
        const float* row = w + (size_t)o * COUT;
        float s = 0.f;
        if (lane < IN_CPG)
            s = row[g * OUT_CPG + lane] + row[g * OUT_CPG + 28 + lane];
        if (g == 4 && lane < 8)
            s += row[504 + lane];
#pragma unroll
        for (int off = 16; off > 0; off >>= 1)
            s += __shfl_xor_sync(0xffffffffu, s, off);
        if (lane == 0) g_we[warp] = s;
    }
}

// ---------------------------------------------------------------------------
// Kernel C (exact R5 structure — the 64-reg / 4-blocks-per-SM sweet spot):
// y[b,o,h,w] = sum_g W_eff[o,g] * s[b,g, h+dy, w+dx]
// Block = (b, h) one output row. 256 threads: w0=(tid&15)*4, och=tid>>4.
// f32x2 packed over PIXELS; weights duplicated+contiguous per o in shared
// (4x LDS.128 + 1x LDS.64 per o). Only delta vs R5: __stcs on y stores
// (write-once stream, evict-first; keeps L2 for s).
// ---------------------------------------------------------------------------
__global__ __launch_bounds__(256) void shiftconv_pw(float* __restrict__ y) {
    __shared__ float w_dup2[COUT * WSTRIDE];             // 40,960 B
    __shared__ float s_sh[GROUPS][W_ + 2];               // 2,376 B (halo cols)

    const int b  = blockIdx.x;                           // 0..31
    const int h  = blockIdx.y;                           // 0..63
    const int tid = threadIdx.x;

    // zero s_sh halo
    for (int i = tid; i < GROUPS * (W_ + 2); i += 256)
        (&s_sh[0][0])[i] = 0.f;
    // weights: g_we is [o][g]; duplicated pair per (o,g), contiguous in o-row
    for (int i = tid; i < COUT * GROUPS; i += 256) {
        int o = i / GROUPS, g = i - o * GROUPS;
        float v = g_we[i];
        w_dup2[o * WSTRIDE + 2 * g]     = v;
        w_dup2[o * WSTRIDE + 2 * g + 1] = v;
    }
    __syncthreads();

    // stage the single s row each group needs: row h + g/3 - 1
    for (int i = tid; i < GROUPS * W_; i += 256) {
        int g = i >> 6, wc = i & 63;
        int hp = h + g / 3 - 1;
        if ((unsigned)hp < (unsigned)H_)
            s_sh[g][wc + 1] = g_s[((size_t)(b * GROUPS + g) << 12) + (hp << 6) + wc];
    }
    __syncthreads();

    const int w0  = (tid & 15) * 4;
    const int och = tid >> 4;                            // 0..15

    // pack shifted s pixel pairs: idx w0+dx+1 = w0 + g%3
    unsigned long long sv2[GROUPS][2];
#pragma unroll
    for (int g = 0; g < GROUPS; g++) {
        const float* r = &s_sh[g][w0 + (g % 3)];
        asm("mov.b64 %0, {%1, %2};" : "=l"(sv2[g][0]) : "f"(r[0]), "f"(r[1]));
        asm("mov.b64 %0, {%1, %2};" : "=l"(sv2[g][1]) : "f"(r[2]), "f"(r[3]));
    }

    float4* yp = reinterpret_cast<float4*>(
        y + ((size_t)b * COUT + och) * HW + h * W_ + w0);
#pragma unroll 4
    for (int oo = 0; oo < 32; oo++) {
        const int o = oo * 16 + och;
        const float* wrow = &w_dup2[o * WSTRIDE];
        // 9 duplicated weight pairs via 4x LDS.128 + 1x LDS.64
        ulonglong2 wA = *reinterpret_cast<const ulonglong2*>(wrow);      // g0,g1
        ulonglong2 wB = *reinterpret_cast<const ulonglong2*>(wrow + 4);  // g2,g3
        ulonglong2 wC = *reinterpret_cast<const ulonglong2*>(wrow + 8);  // g4,g5
        ulonglong2 wD = *reinterpret_cast<const ulonglong2*>(wrow + 12); // g6,g7
        unsigned long long wE =
            *reinterpret_cast<const unsigned long long*>(wrow + 16);     // g8

        unsigned long long a0 = 0ull, a1 = 0ull;
        asm("fma.rn.f32x2 %0, %1, %2, %0;" : "+l"(a0) : "l"(wA.x), "l"(sv2[0][0]));
        asm("fma.rn.f32x2 %0, %1, %2, %0;" : "+l"(a1) : "l"(wA.x), "l"(sv2[0][1]));
        asm("fma.rn.f32x2 %0, %1, %2, %0;" : "+l"(a0) : "l"(wA.y), "l"(sv2[1][0]));
        asm("fma.rn.f32x2 %0, %1, %2, %0;" : "+l"(a1) : "l"(wA.y), "l"(sv2[1][1]));
        asm("fma.rn.f32x2 %0, %1, %2, %0;" : "+l"(a0) : "l"(wB.x), "l"(sv2[2][0]));
        asm("fma.rn.f32x2 %0, %1, %2, %0;" : "+l"(a1) : "l"(wB.x), "l"(sv2[2][1]));
        asm("fma.rn.f32x2 %0, %1, %2, %0;" : "+l"(a0) : "l"(wB.y), "l"(sv2[3][0]));
        asm("fma.rn.f32x2 %0, %1, %2, %0;" : "+l"(a1) : "l"(wB.y), "l"(sv2[3][1]));
        asm("fma.rn.f32x2 %0, %1, %2, %0;" : "+l"(a0) : "l"(wC.x), "l"(sv2[4][0]));
        asm("fma.rn.f32x2 %0, %1, %2, %0;" : "+l"(a1) : "l"(wC.x), "l"(sv2[4][1]));
        asm("fma.rn.f32x2 %0, %1, %2, %0;" : "+l"(a0) : "l"(wC.y), "l"(sv2[5][0]));
        asm("fma.rn.f32x2 %0, %1, %2, %0;" : "+l"(a1) : "l"(wC.y), "l"(sv2[5][1]));
        asm("fma.rn.f32x2 %0, %1, %2, %0;" : "+l"(a0) : "l"(wD.x), "l"(sv2[6][0]));
        asm("fma.rn.f32x2 %0, %1, %2, %0;" : "+l"(a1) : "l"(wD.x), "l"(sv2[6][1]));
        asm("fma.rn.f32x2 %0, %1, %2, %0;" : "+l"(a0) : "l"(wD.y), "l"(sv2[7][0]));
        asm("fma.rn.f32x2 %0, %1, %2, %0;" : "+l"(a1) : "l"(wD.y), "l"(sv2[7][1]));
        asm("fma.rn.f32x2 %0, %1, %2, %0;" : "+l"(a0) : "l"(wE),   "l"(sv2[8][0]));
        asm("fma.rn.f32x2 %0, %1, %2, %0;" : "+l"(a1) : "l"(wE),   "l"(sv2[8][1]));

        float4 out;
        asm("mov.b64 {%0, %1}, %2;" : "=f"(out.x), "=f"(out.y) : "l"(a0));
        asm("mov.b64 {%0, %1}, %2;" : "=f"(out.z), "=f"(out.w) : "l"(a1));
        __stcs(yp + (size_t)oo * 16 * (HW / 4), out);    // streaming store, o stride 16
    }
}

// ---------------------------------------------------------------------------
extern "C" void kernel_launch(void* const* d_in, const int* in_sizes, int n_in,
                              void* d_out, int out_size) {
    const float* x = (const float*)d_in[0];
    const float* w = (const float*)d_in[1];
    if (n_in >= 2 && in_sizes[0] == COUT * COUT) {       // order safety
        const float* t = x; x = w; w = t;
    }
    float* y = (float*)d_out;

    shiftconv_prep<<<PREP_BLOCKS, 256>>>((const float4*)x, w);
    shiftconv_pw<<<dim3(B_, H_), 256>>>(y);
}